// round 3
// baseline (speedup 1.0000x reference)
#include <cuda_runtime.h>
#include <cstdint>

#define N_ACT 80
#define M_CON 85
#define NP1   81
#define PDHG_ITERS 200
#define POWER_ITERS 20

// Per-problem shared-memory block (two of these per CTA).
struct HalfSmem {
    float vec[84];       // v / z_bar (0..80 used), float4-aligned
    float y[88];         // Gv / y    (0..84 used)
    float x0[80];
    float dv[80];
    float d[88];
    float red[4];
    float As[M_CON * 81];  // pitch 81 (odd) -> conflict-free column reads
    float pad[3];          // round struct to 16B multiple
};

static __device__ __forceinline__ void hsync(int id) {
    // Named barrier over this problem-half's 3 warps (96 threads).
    asm volatile("bar.sync %0, 96;" :: "r"(id) : "memory");
}

static __device__ __forceinline__ float warp_sum(float v) {
    #pragma unroll
    for (int off = 16; off > 0; off >>= 1)
        v += __shfl_xor_sync(0xffffffffu, v, off);
    return v;
}
static __device__ __forceinline__ float warp_min(float v) {
    #pragma unroll
    for (int off = 16; off > 0; off >>= 1)
        v = fminf(v, __shfl_xor_sync(0xffffffffu, v, off));
    return v;
}

__global__ __launch_bounds__(192, 2)
void acp_kernel(const float* __restrict__ xhat,
                const float* __restrict__ Aglob,
                const float* __restrict__ bglob,
                float* __restrict__ out,
                int P)
{
    extern __shared__ HalfSmem Hs[];

    const int t    = threadIdx.x;        // 0..191
    const int half = t >> 6 >= 1 ? (t >= 96) : 0; // avoid div; t>=96 -> half 1
    const int u    = t - (half ? 96 : 0);          // 0..95 within half
    const int wid  = u >> 5;
    const int lane = u & 31;
    const int prob = blockIdx.x * 2 + half;
    if (prob >= P) return;

    HalfSmem* H = &Hs[half];
    const int bid = half + 1;            // named barrier ids 1 and 2

    const float* Ap = Aglob + (size_t)prob * (M_CON * N_ACT);

    // ---- stage A into shared (coalesced within the half) ----
    for (int i = u; i < M_CON * N_ACT; i += 96) {
        int r = i / N_ACT;
        int c = i - r * N_ACT;
        H->As[r * 81 + c] = Ap[i];
    }
    if (u < 88) H->y[u] = 0.0f;
    if (u < 84) H->vec[u] = (u < NP1) ? 1.0f : 0.0f;   // power-iter v0 = ones
    hsync(bid);

    // ---- register-resident G in both orientations ----
    float rowA[N_ACT];   // row u of A   (u < 85)
    float colA[M_CON];   // column u of G (u < 81; col 80 = d)
    float dval = 0.0f, bval = 0.0f;

    if (u < M_CON) {
        float s0 = 0.0f, s1 = 0.0f, s2 = 0.0f, s3 = 0.0f;
        #pragma unroll
        for (int k = 0; k < N_ACT; k += 4) {
            float a0 = H->As[u * 81 + k + 0];
            float a1 = H->As[u * 81 + k + 1];
            float a2 = H->As[u * 81 + k + 2];
            float a3 = H->As[u * 81 + k + 3];
            rowA[k + 0] = a0; rowA[k + 1] = a1;
            rowA[k + 2] = a2; rowA[k + 3] = a3;
            s0 = fmaf(a0, a0, s0); s1 = fmaf(a1, a1, s1);
            s2 = fmaf(a2, a2, s2); s3 = fmaf(a3, a3, s3);
        }
        dval = fmaxf(sqrtf((s0 + s1) + (s2 + s3)), 1e-12f);
        H->d[u] = dval;
        bval = bglob[(size_t)prob * M_CON + u];
    }
    hsync(bid);
    if (u < N_ACT) {
        #pragma unroll
        for (int j = 0; j < M_CON; j++) colA[j] = H->As[j * 81 + u];
    } else if (u == N_ACT) {
        #pragma unroll
        for (int j = 0; j < M_CON; j++) colA[j] = H->d[j];
    }

    // dot over 81 terms (rowG[80] = dval) with 4 accumulators
    #define ROW_DOT(res, VEC)                                          \
    {                                                                  \
        float a0 = 0.0f, a1 = 0.0f, a2 = 0.0f, a3 = 0.0f;              \
        const float4* v4_ = reinterpret_cast<const float4*>(VEC);      \
        _Pragma("unroll")                                              \
        for (int q = 0; q < 20; q++) {                                 \
            float4 vv = v4_[q];                                        \
            a0 = fmaf(rowA[4*q+0], vv.x, a0);                          \
            a1 = fmaf(rowA[4*q+1], vv.y, a1);                          \
            a2 = fmaf(rowA[4*q+2], vv.z, a2);                          \
            a3 = fmaf(rowA[4*q+3], vv.w, a3);                          \
        }                                                              \
        res = ((a0 + a1) + (a2 + a3)) + dval * (VEC)[80];              \
    }
    // dot over 85 terms with 4 accumulators
    #define COL_DOT(res, VEC)                                          \
    {                                                                  \
        float a0 = 0.0f, a1 = 0.0f, a2 = 0.0f, a3 = 0.0f;              \
        const float4* v4_ = reinterpret_cast<const float4*>(VEC);      \
        _Pragma("unroll")                                              \
        for (int q = 0; q < 21; q++) {                                 \
            float4 vv = v4_[q];                                        \
            a0 = fmaf(colA[4*q+0], vv.x, a0);                          \
            a1 = fmaf(colA[4*q+1], vv.y, a1);                          \
            a2 = fmaf(colA[4*q+2], vv.z, a2);                          \
            a3 = fmaf(colA[4*q+3], vv.w, a3);                          \
        }                                                              \
        res = ((a0 + a1) + (a2 + a3)) + colA[84] * (VEC)[84];          \
    }

    // ---- power iteration: v <- GT(G v) / ||GT(G v)|| ----
    for (int pi = 0; pi < POWER_ITERS; pi++) {
        if (u < M_CON) {
            float g; ROW_DOT(g, H->vec);
            H->y[u] = g;
        }
        hsync(bid);
        float w = 0.0f;
        if (u < NP1) { COL_DOT(w, H->y); }
        float ss = warp_sum(w * w);
        if (lane == 0) H->red[wid] = ss;
        hsync(bid);
        float nrm = sqrtf(H->red[0] + H->red[1] + H->red[2]) + 1e-12f;
        if (u < NP1) H->vec[u] = w / nrm;
        hsync(bid);
    }
    // L = ||G v||
    {
        float g = 0.0f;
        if (u < M_CON) { ROW_DOT(g, H->vec); }
        float ss = warp_sum(g * g);
        if (lane == 0) H->red[wid] = ss;
        hsync(bid);
    }
    const float Lnrm = sqrtf(H->red[0] + H->red[1] + H->red[2]);
    const float tau  = 0.9f / fmaxf(Lnrm, 1e-6f);   // sigma == tau

    // ---- PDHG: 200 fixed iterations ----
    if (u < 88) H->y[u] = 0.0f;     // y = 0
    float zv = 0.0f, yv = 0.0f;     // z = 0
    hsync(bid);

    for (int it = 0; it < PDHG_ITERS; it++) {
        if (u < NP1) {
            float gty; COL_DOT(gty, H->y);
            float cterm = (u == N_ACT) ? -1.0f : 0.0f;
            float znew = fmaxf(zv - tau * (cterm + gty), 0.0f);
            H->vec[u] = 2.0f * znew - zv;   // z_bar
            zv = znew;
        }
        hsync(bid);
        if (u < M_CON) {
            float gz; ROW_DOT(gz, H->vec);
            yv = fmaxf(yv + tau * (gz - bval), 0.0f);
            H->y[u] = yv;
        }
        hsync(bid);
    }

    // ---- alpha map ----
    if (u < N_ACT) {
        H->x0[u] = zv;
        H->dv[u] = xhat[(size_t)prob * N_ACT + u] - zv;
    }
    hsync(bid);

    const float INF = __int_as_float(0x7f800000);
    float ai = INF;
    if (u < M_CON) {
        float x0a = 0.0f, x0b = 0.0f, da = 0.0f, db = 0.0f;
        const float4* x4 = reinterpret_cast<const float4*>(H->x0);
        const float4* d4 = reinterpret_cast<const float4*>(H->dv);
        #pragma unroll
        for (int q = 0; q < 20; q++) {
            float4 xv = x4[q];
            float4 dv = d4[q];
            x0a = fmaf(rowA[4*q+0], xv.x, x0a);
            x0b = fmaf(rowA[4*q+1], xv.y, x0b);
            x0a = fmaf(rowA[4*q+2], xv.z, x0a);
            x0b = fmaf(rowA[4*q+3], xv.w, x0b);
            da  = fmaf(rowA[4*q+0], dv.x, da);
            db  = fmaf(rowA[4*q+1], dv.y, db);
            da  = fmaf(rowA[4*q+2], dv.z, da);
            db  = fmaf(rowA[4*q+3], dv.w, db);
        }
        float ax0 = x0a + x0b;
        float ad  = da + db;
        float slack = fmaxf(bval - ax0, 0.0f);
        ai = (ad > 0.0f) ? (slack / (ad + 1e-12f)) : INF;
    }
    ai = warp_min(ai);
    if (lane == 0) H->red[wid] = ai;
    hsync(bid);
    float alpha = fminf(H->red[0], fminf(H->red[1], H->red[2]));
    if (!isfinite(alpha)) alpha = 1.0f;
    alpha = fminf(fmaxf(alpha - 1e-9f, 0.0f), 1.0f);

    if (u < N_ACT)
        out[(size_t)prob * N_ACT + u] = fmaxf(H->x0[u] + alpha * H->dv[u], 0.0f);

    #undef ROW_DOT
    #undef COL_DOT
}

extern "C" void kernel_launch(void* const* d_in, const int* in_sizes, int n_in,
                              void* d_out, int out_size)
{
    const float* xhat = (const float*)d_in[0];
    const float* A    = (const float*)d_in[1];
    const float* b    = (const float*)d_in[2];
    float* out        = (float*)d_out;
    int P = in_sizes[0] / N_ACT;            // 64*16 = 1024 problems

    size_t smem = 2 * sizeof(HalfSmem);     // two problems per CTA
    cudaFuncSetAttribute(acp_kernel,
                         cudaFuncAttributeMaxDynamicSharedMemorySize,
                         (int)smem);

    int grid = (P + 1) / 2;                 // 512
    acp_kernel<<<grid, 192, smem>>>(xhat, A, b, out, P);
}